// round 12
// baseline (speedup 1.0000x reference)
#include <cuda_runtime.h>
#include <cuda_fp16.h>
#include <cstdint>

// ---------------------------------------------------------------------------
// Problem constants
// ---------------------------------------------------------------------------
#define BATCH 8
#define TT 2048
#define CH 512
#define MTOT (BATCH*TT)          // 16384
#define NTILES (TT/128)          // 16 row tiles
#define INV_SQRTK 0.04419417382415922f

// ---------------------------------------------------------------------------
// CTA tile 128(M) x 256(N), K-chunk 32. 8 warps in 2(M)x4(N), warp tile 64x64.
// Shared memory (dynamic):
//   [0:2048)          reduction scratch (scores)
//   [2048: +3*24KB)   three stages x {A: 128x32 (8KB), B: 256x32 (16KB)}
// 64B rows, SW64 swizzled. ~74KB -> 1 CTA/SM (reg-limited anyway: ~190 regs).
// ---------------------------------------------------------------------------
#define SM_RED 0
#define SM_BUF 2048
#define TA_BYTES 8192
#define TB_BYTES 16384
#define STAGE_BYTES (TA_BYTES + TB_BYTES)      // 24576
#define NSTAGE 3
#define SMEM_TOTAL (2048 + NSTAGE*STAGE_BYTES) // 75776

// ---------------------------------------------------------------------------
// Device scratch (no allocation allowed). Pure fp16 operands.
// ---------------------------------------------------------------------------
__device__ __align__(16) __half g_xh[(size_t)MTOT*CH];
__device__ __align__(16) __half g_wT[(size_t)3*CH*CH];
__device__ __align__(16) __half g_qh[(size_t)MTOT*CH];
__device__ __align__(16) __half g_kh[(size_t)MTOT*CH];
__device__ __align__(16) float  g_v[(size_t)MTOT*CH];
__device__ __align__(16) __half g_E[(size_t)BATCH*TT*TT];
__device__ __align__(16) __half g_vT[(size_t)BATCH*CH*TT];
__device__ float g_part[BATCH*NTILES*TT];
__device__ float g_rcol[BATCH*TT];

// ---------------------------------------------------------------------------
// PTX helpers — portable (sm_80-level) PTX, legal at compute_103
// ---------------------------------------------------------------------------
__device__ __forceinline__ uint32_t smem_u32(const void* p) {
    uint32_t a;
    asm("{ .reg .u64 t; cvta.to.shared.u64 t, %1; cvt.u32.u64 %0, t; }"
        : "=r"(a) : "l"(p));
    return a;
}

__device__ __forceinline__ void cp16(uint32_t s, const void* g) {
    asm volatile("cp.async.cg.shared.global [%0], [%1], 16;" :: "r"(s), "l"(g));
}
__device__ __forceinline__ void cp_commit() {
    asm volatile("cp.async.commit_group;" ::: "memory");
}
template<int N> __device__ __forceinline__ void cp_wait() {
    asm volatile("cp.async.wait_group %0;" :: "n"(N) : "memory");
}

__device__ __forceinline__ void ldm4(uint32_t* r, uint32_t a) {
    asm volatile("ldmatrix.sync.aligned.m8n8.x4.shared.b16 {%0,%1,%2,%3}, [%4];"
        : "=r"(r[0]), "=r"(r[1]), "=r"(r[2]), "=r"(r[3]) : "r"(a));
}

__device__ __forceinline__ void mma16816(float* c, const uint32_t* a, const uint32_t* b) {
    asm volatile(
        "mma.sync.aligned.m16n8k16.row.col.f32.f16.f16.f32 "
        "{%0,%1,%2,%3}, {%4,%5,%6,%7}, {%8,%9}, {%0,%1,%2,%3};"
        : "+f"(c[0]), "+f"(c[1]), "+f"(c[2]), "+f"(c[3])
        : "r"(a[0]), "r"(a[1]), "r"(a[2]), "r"(a[3]), "r"(b[0]), "r"(b[1]));
}

// SW64 swizzle for 64-byte rows: XOR 16B-chunk bits with row bits.
__device__ __forceinline__ uint32_t sw64(uint32_t off, uint32_t row) {
    return off ^ ((row * 8u) & 0x30u);
}

// ---------------------------------------------------------------------------
// Stage loader: A 128x32 fp16 + B 256x32 fp16 (64B rows), SW64, cp.async
// ---------------------------------------------------------------------------
__device__ __forceinline__ void load_stage(
    uint32_t sbuf,
    const __half* __restrict__ aH, int lda,
    const __half* __restrict__ bH, int ldb,
    int kofs, int tid)
{
    #pragma unroll
    for (int i = 0; i < 2; i++) {            // A: 512 cp16
        const int u = tid + i*256;
        const int row = u >> 2, c16 = u & 3;
        const uint32_t so = sw64((uint32_t)(row*64 + c16*16), (uint32_t)row);
        cp16(sbuf + so, aH + (size_t)row * lda + kofs + c16*8);
    }
    #pragma unroll
    for (int i = 0; i < 4; i++) {            // B: 1024 cp16
        const int u = tid + i*256;
        const int row = u >> 2, c16 = u & 3;
        const uint32_t so = sw64((uint32_t)(row*64 + c16*16), (uint32_t)row);
        cp16(sbuf + TA_BYTES + so, bH + (size_t)row * ldb + kofs + c16*8);
    }
}

// ---------------------------------------------------------------------------
// Compute one K=32 stage. Warp tile 64x64: per kk, 8 ldm4 feed 32 MMAs.
// acc[4][8][4]  (4 m16 x 8 n8 frags)
// ---------------------------------------------------------------------------
__device__ __forceinline__ void compute_stage(uint32_t sbuf, float acc[4][8][4],
                                              int lane, int wm, int wn)
{
    const int arow0 = wm*64 + (lane & 15);
    const uint32_t aX = (uint32_t)(lane & 16);
    const int brow0 = wn*64 + (lane & 7) + ((lane & 16) >> 1);
    const uint32_t bX = (uint32_t)((lane & 8) << 1);

    #pragma unroll
    for (int kk = 0; kk < 2; kk++) {
        const uint32_t kb = (uint32_t)kk * 32;
        uint32_t ah[4][4], bh[4][4];
        #pragma unroll
        for (int g = 0; g < 4; g++) {
            const uint32_t r = (uint32_t)(brow0 + g*16);
            ldm4(bh[g], sbuf + TA_BYTES + sw64(r*64 + kb + bX, r));
        }
        #pragma unroll
        for (int mi = 0; mi < 4; mi++) {
            const uint32_t r = (uint32_t)(arow0 + mi*16);
            ldm4(ah[mi], sbuf + sw64(r*64 + kb + aX, r));
        }
        #pragma unroll
        for (int mi = 0; mi < 4; mi++)
            #pragma unroll
            for (int nj = 0; nj < 8; nj++)
                mma16816(acc[mi][nj], ah[mi], &bh[nj>>1][(nj&1)*2]);
    }
}

// ---------------------------------------------------------------------------
// 3-stage single-barrier pipelined mainloop (K = NC*32)
// ---------------------------------------------------------------------------
__device__ __forceinline__ void gemm_mainloop(
    const __half* __restrict__ aH, int lda,
    const __half* __restrict__ bH, int ldb,
    int NC, uint32_t sbase, float acc[4][8][4], int tid)
{
    const int lane = tid & 31, w = tid >> 5;
    const int wm = w >> 2, wn = w & 3;

    load_stage(sbase + SM_BUF, aH, lda, bH, ldb, 0, tid);
    cp_commit();
    if (NC > 1)
        load_stage(sbase + SM_BUF + STAGE_BYTES, aH, lda, bH, ldb, 32, tid);
    cp_commit();

    int s_cur = 0, s_nxt = 2 % NSTAGE;
    for (int c = 0; c < NC; c++) {
        cp_wait<1>();
        __syncthreads();
        if (c + 2 < NC)
            load_stage(sbase + SM_BUF + (uint32_t)s_nxt * STAGE_BYTES,
                       aH, lda, bH, ldb, (c+2)*32, tid);
        cp_commit();
        compute_stage(sbase + SM_BUF + (uint32_t)s_cur * STAGE_BYTES, acc, lane, wm, wn);
        s_cur = (s_cur + 1 == NSTAGE) ? 0 : s_cur + 1;
        s_nxt = (s_nxt + 1 == NSTAGE) ? 0 : s_nxt + 1;
    }
    __syncthreads();
}

// ---------------------------------------------------------------------------
extern __shared__ char dynsmem[];

// Kernel: QKV projection. grid(2 ntile, 128 mtile, 3 qkv)
__global__ __launch_bounds__(256, 1)
void proj_tc(const float* __restrict__ bq, const float* __restrict__ bk,
             const float* __restrict__ bv)
{
    const int z = blockIdx.z;
    const int m0 = blockIdx.y * 128, n0 = blockIdx.x * 256;
    const uint32_t sbase = smem_u32(dynsmem);
    const int tid = threadIdx.x;

    float acc[4][8][4];
    #pragma unroll
    for (int a = 0; a < 4; a++)
        #pragma unroll
        for (int b = 0; b < 8; b++)
            #pragma unroll
            for (int c = 0; c < 4; c++) acc[a][b][c] = 0.f;

    gemm_mainloop(g_xh + (size_t)m0 * CH, CH,
                  g_wT + (size_t)z*CH*CH + (size_t)n0 * CH, CH,
                  CH/32, sbase, acc, tid);

    const float* bias = (z == 0) ? bq : (z == 1) ? bk : bv;
    const int lane = tid & 31, w = tid >> 5;
    const int wm = w >> 2, wn = w & 3;

    #pragma unroll
    for (int mi = 0; mi < 4; mi++) {
        const int r0 = m0 + wm*64 + mi*16 + (lane >> 2);
        #pragma unroll
        for (int nj = 0; nj < 8; nj++) {
            const int n = n0 + wn*64 + nj*8 + (lane & 3)*2;
            const float b0 = bias[n], b1 = bias[n+1];
            const float v00 = acc[mi][nj][0] + b0, v01 = acc[mi][nj][1] + b1;
            const float v10 = acc[mi][nj][2] + b0, v11 = acc[mi][nj][3] + b1;
            if (z < 2) {
                __half* oH = (z == 0) ? g_qh : g_kh;
                *(__half2*)(oH + (size_t)r0*CH + n) =
                    __halves2half2(__float2half(v00), __float2half(v01));
                *(__half2*)(oH + (size_t)(r0+8)*CH + n) =
                    __halves2half2(__float2half(v10), __float2half(v11));
            } else {
                *(float2*)(g_v + (size_t)r0*CH + n)     = make_float2(v00, v01);
                *(float2*)(g_v + (size_t)(r0+8)*CH + n) = make_float2(v10, v11);
            }
        }
    }
}

// Kernel: causal scores -> exp -> E (fp16) + column partial sums.
// Tiles 128(t) x 256(s): per row-tile it, col tiles js = 0..(it>>1) -> 72/batch.
__global__ __launch_bounds__(256, 1)
void scores_tc()
{
    const int b = blockIdx.y;
    int idx = blockIdx.x;
    int it = 0, cum = 0;
    while (cum + (it >> 1) + 1 <= idx) { cum += (it >> 1) + 1; it++; }
    const int js = idx - cum;
    const int t0 = it * 128, s0 = js * 256;

    const uint32_t sbase = smem_u32(dynsmem);
    const int tid = threadIdx.x;

    float acc[4][8][4];
    #pragma unroll
    for (int a = 0; a < 4; a++)
        #pragma unroll
        for (int c = 0; c < 8; c++)
            #pragma unroll
            for (int d = 0; d < 4; d++) acc[a][c][d] = 0.f;

    gemm_mainloop(g_qh + ((size_t)b*TT + t0)*CH, CH,
                  g_kh + ((size_t)b*TT + s0)*CH, CH,
                  CH/32, sbase, acc, tid);

    const int lane = tid & 31, w = tid >> 5;
    const int wm = w >> 2, wn = w & 3;
    float* red = (float*)dynsmem;   // [2][256]

    float psum[8][2];
    #pragma unroll
    for (int nj = 0; nj < 8; nj++) { psum[nj][0] = 0.f; psum[nj][1] = 0.f; }

    const bool diag = (js == (it >> 1));
    #pragma unroll
    for (int mi = 0; mi < 4; mi++) {
        const int ta = t0 + wm*64 + mi*16 + (lane >> 2);
        const int tb = ta + 8;
        #pragma unroll
        for (int nj = 0; nj < 8; nj++) {
            const int s = s0 + wn*64 + nj*8 + (lane & 3)*2;
            float e00 = __expf(acc[mi][nj][0] * INV_SQRTK);
            float e01 = __expf(acc[mi][nj][1] * INV_SQRTK);
            float e10 = __expf(acc[mi][nj][2] * INV_SQRTK);
            float e11 = __expf(acc[mi][nj][3] * INV_SQRTK);
            if (diag) {
                if (s   > ta) e00 = 0.f;
                if (s+1 > ta) e01 = 0.f;
                if (s   > tb) e10 = 0.f;
                if (s+1 > tb) e11 = 0.f;
            }
            const size_t oa = ((size_t)b*TT + ta)*TT + s;
            const size_t ob = ((size_t)b*TT + tb)*TT + s;
            *(__half2*)(g_E + oa) = __halves2half2(__float2half(e00), __float2half(e01));
            *(__half2*)(g_E + ob) = __halves2half2(__float2half(e10), __float2half(e11));
            psum[nj][0] += e00 + e10;
            psum[nj][1] += e01 + e11;
        }
    }
    #pragma unroll
    for (int ofs = 4; ofs <= 16; ofs <<= 1)
        #pragma unroll
        for (int nj = 0; nj < 8; nj++) {
            psum[nj][0] += __shfl_xor_sync(0xffffffff, psum[nj][0], ofs);
            psum[nj][1] += __shfl_xor_sync(0xffffffff, psum[nj][1], ofs);
        }
    if (lane < 4) {
        #pragma unroll
        for (int nj = 0; nj < 8; nj++) {
            const int col = wn*64 + nj*8 + lane*2;
            red[wm*256 + col]     = psum[nj][0];
            red[wm*256 + col + 1] = psum[nj][1];
        }
    }
    __syncthreads();
    // g_part[(b, it) band, column s0+tid]
    g_part[(size_t)(b*NTILES + it)*TT + s0 + tid] = red[tid] + red[256 + tid];
}

// Kernel: reduce column partials -> reciprocal colsum
__global__ void colsum_kernel()
{
    const int i = blockIdx.x * blockDim.x + threadIdx.x;  // b*TT + s
    if (i >= BATCH*TT) return;
    const int b = i >> 11, s = i & (TT - 1);
    float sum = 0.f;
    for (int it = s >> 7; it < NTILES; it++)
        sum += g_part[(size_t)(b*NTILES + it)*TT + s];
    g_rcol[i] = 1.0f / sum;
}

// Kernel: v -> vT scaled by rcol, fp16. grid(64 s-tiles, 16 n-tiles, 8)
__global__ void convvt_kernel()
{
    __shared__ float tile[32][33];
    const int b = blockIdx.z;
    const int s0 = blockIdx.x * 32, n0 = blockIdx.y * 32;
    const int tx = threadIdx.x, ty = threadIdx.y;
    const int s = s0 + ty;
    const float scale = g_rcol[b*TT + s];
    tile[ty][tx] = g_v[((size_t)b*TT + s) * CH + n0 + tx] * scale;
    __syncthreads();
    const float v = tile[tx][ty];
    const size_t o = ((size_t)b*CH + n0 + ty) * TT + s0 + tx;
    g_vT[o] = __float2half(v);
}

// Kernel: read = E * vT'. grid(2 ntile, 16 ttile, 8 batch)
// it reversed so heavy (late-row) tiles launch first.
__global__ __launch_bounds__(256, 1)
void read_tc(float* __restrict__ out)
{
    const int b = blockIdx.z;
    const int it = NTILES - 1 - blockIdx.y;
    const int t0 = it * 128, n0 = blockIdx.x * 256;
    const uint32_t sbase = smem_u32(dynsmem);
    const int tid = threadIdx.x;

    float acc[4][8][4];
    #pragma unroll
    for (int a = 0; a < 4; a++)
        #pragma unroll
        for (int c = 0; c < 8; c++)
            #pragma unroll
            for (int d = 0; d < 4; d++) acc[a][c][d] = 0.f;

    gemm_mainloop(g_E + ((size_t)b*TT + t0)*TT, TT,
                  g_vT + ((size_t)b*CH + n0)*TT, TT,
                  (it + 1) * 4, sbase, acc, tid);

    const int lane = tid & 31, w = tid >> 5;
    const int wm = w >> 2, wn = w & 3;

    #pragma unroll
    for (int mi = 0; mi < 4; mi++) {
        const int t = t0 + wm*64 + mi*16 + (lane >> 2);
        #pragma unroll
        for (int nj = 0; nj < 8; nj++) {
            const int n = n0 + wn*64 + nj*8 + (lane & 3)*2;
            float* oa = out + ((size_t)(b*TT + t)) * 1024 + 512 + n;
            float* ob = out + ((size_t)(b*TT + t + 8)) * 1024 + 512 + n;
            *(float2*)oa = make_float2(acc[mi][nj][0], acc[mi][nj][1]);
            *(float2*)ob = make_float2(acc[mi][nj][2], acc[mi][nj][3]);
        }
    }
}

// ---------------------------------------------------------------------------
// x prep: copy x into out[:, 0:512] AND convert to fp16 in one pass
// ---------------------------------------------------------------------------
__global__ void xprep_kernel(const float* __restrict__ x, float* __restrict__ out)
{
    const size_t i = (size_t)blockIdx.x * blockDim.x + threadIdx.x;  // float4 idx
    const int row = (int)(i >> 7), c4 = (int)(i & 127);
    const float4 v = ((const float4*)x)[i];
    ((float4*)out)[(size_t)row * 256 + c4] = v;
    __align__(8) __half h[4];
    h[0] = __float2half(v.x); h[1] = __float2half(v.y);
    h[2] = __float2half(v.z); h[3] = __float2half(v.w);
    ((uint2*)g_xh)[i] = *(const uint2*)h;
}

__global__ void convw_kernel(const float* __restrict__ Wq,
                             const float* __restrict__ Wk,
                             const float* __restrict__ Wv)
{
    __shared__ float tile[32][33];
    const float* W = (blockIdx.z == 0) ? Wq : (blockIdx.z == 1) ? Wk : Wv;
    const int k0 = blockIdx.x * 32, n0 = blockIdx.y * 32;
    const int tx = threadIdx.x, ty = threadIdx.y;
    tile[ty][tx] = W[(size_t)(k0 + ty) * CH + n0 + tx];
    __syncthreads();
    const float v = tile[tx][ty];   // = W[k0+tx][n0+ty]
    const size_t o = (size_t)blockIdx.z*CH*CH + (size_t)(n0 + ty) * CH + k0 + tx;
    g_wT[o] = __float2half(v);
}

// ---------------------------------------------------------------------------
extern "C" void kernel_launch(void* const* d_in, const int* in_sizes, int n_in,
                              void* d_out, int out_size)
{
    const float* x  = (const float*)d_in[0];
    const float* Wq = (const float*)d_in[1];
    const float* bq = (const float*)d_in[2];
    const float* Wk = (const float*)d_in[3];
    const float* bk = (const float*)d_in[4];
    const float* Wv = (const float*)d_in[5];
    const float* bv = (const float*)d_in[6];
    float* out = (float*)d_out;

    cudaFuncSetAttribute(proj_tc,   cudaFuncAttributeMaxDynamicSharedMemorySize, SMEM_TOTAL);
    cudaFuncSetAttribute(scores_tc, cudaFuncAttributeMaxDynamicSharedMemorySize, SMEM_TOTAL);
    cudaFuncSetAttribute(read_tc,   cudaFuncAttributeMaxDynamicSharedMemorySize, SMEM_TOTAL);

    xprep_kernel<<<8192, 256>>>(x, out);
    convw_kernel<<<dim3(16, 16, 3), dim3(32, 32)>>>(Wq, Wk, Wv);
    proj_tc<<<dim3(2, 128, 3), 256, SMEM_TOTAL>>>(bq, bk, bv);
    scores_tc<<<dim3(72, BATCH), 256, SMEM_TOTAL>>>();
    colsum_kernel<<<64, 256>>>();
    convvt_kernel<<<dim3(64, 16, 8), dim3(32, 32)>>>();
    read_tc<<<dim3(2, NTILES, BATCH), 256, SMEM_TOTAL>>>(out);
}

// round 13
// speedup vs baseline: 1.0633x; 1.0633x over previous
#include <cuda_runtime.h>
#include <cuda_fp16.h>
#include <cstdint>

// ---------------------------------------------------------------------------
// Problem constants
// ---------------------------------------------------------------------------
#define BATCH 8
#define TT 2048
#define CH 512
#define MTOT (BATCH*TT)          // 16384
#define NTILES (TT/128)          // 16 row tiles
#define INV_SQRTK 0.04419417382415922f

// ---------------------------------------------------------------------------
// CTA: 512 threads, 16 warps in 4(M)x4(N), warp tile 32x32 -> CTA tile 128x128.
// K-chunk 32. Both k16-steps' fragments prefetched upfront (acc only 32 regs).
// Shared memory (dynamic):
//   [0:2048)          reduction scratch (scores)
//   [2048: +3*16KB)   three stages x {A: 128x32 (8KB), B: 128x32 (8KB)}
// 64B rows, SW64 swizzled. ~50KB, 1 CTA/SM (512 thr, ~90 regs).
// ---------------------------------------------------------------------------
#define SM_RED 0
#define SM_BUF 2048
#define T_BYTES 8192
#define STAGE_BYTES (2*T_BYTES)
#define NSTAGE 3
#define SMEM_TOTAL (2048 + NSTAGE*STAGE_BYTES)   // 51200

// ---------------------------------------------------------------------------
// Device scratch (no allocation allowed). Pure fp16 operands.
// ---------------------------------------------------------------------------
__device__ __align__(16) __half g_xh[(size_t)MTOT*CH];
__device__ __align__(16) __half g_wT[(size_t)3*CH*CH];
__device__ __align__(16) __half g_qh[(size_t)MTOT*CH];
__device__ __align__(16) __half g_kh[(size_t)MTOT*CH];
__device__ __align__(16) float  g_v[(size_t)MTOT*CH];
__device__ __align__(16) __half g_E[(size_t)BATCH*TT*TT];
__device__ __align__(16) __half g_vT[(size_t)BATCH*CH*TT];
__device__ float g_part[BATCH*NTILES*TT];
__device__ float g_rcol[BATCH*TT];

// ---------------------------------------------------------------------------
// PTX helpers — portable (sm_80-level) PTX, legal at compute_103
// ---------------------------------------------------------------------------
__device__ __forceinline__ uint32_t smem_u32(const void* p) {
    uint32_t a;
    asm("{ .reg .u64 t; cvta.to.shared.u64 t, %1; cvt.u32.u64 %0, t; }"
        : "=r"(a) : "l"(p));
    return a;
}

__device__ __forceinline__ void cp16(uint32_t s, const void* g) {
    asm volatile("cp.async.cg.shared.global [%0], [%1], 16;" :: "r"(s), "l"(g));
}
__device__ __forceinline__ void cp_commit() {
    asm volatile("cp.async.commit_group;" ::: "memory");
}
template<int N> __device__ __forceinline__ void cp_wait() {
    asm volatile("cp.async.wait_group %0;" :: "n"(N) : "memory");
}

__device__ __forceinline__ void ldm4(uint32_t* r, uint32_t a) {
    asm volatile("ldmatrix.sync.aligned.m8n8.x4.shared.b16 {%0,%1,%2,%3}, [%4];"
        : "=r"(r[0]), "=r"(r[1]), "=r"(r[2]), "=r"(r[3]) : "r"(a));
}

__device__ __forceinline__ void mma16816(float* c, const uint32_t* a, const uint32_t* b) {
    asm volatile(
        "mma.sync.aligned.m16n8k16.row.col.f32.f16.f16.f32 "
        "{%0,%1,%2,%3}, {%4,%5,%6,%7}, {%8,%9}, {%0,%1,%2,%3};"
        : "+f"(c[0]), "+f"(c[1]), "+f"(c[2]), "+f"(c[3])
        : "r"(a[0]), "r"(a[1]), "r"(a[2]), "r"(a[3]), "r"(b[0]), "r"(b[1]));
}

// SW64 swizzle for 64-byte rows: XOR 16B-chunk bits with row bits.
__device__ __forceinline__ uint32_t sw64(uint32_t off, uint32_t row) {
    return off ^ ((row * 8u) & 0x30u);
}

// ---------------------------------------------------------------------------
// Stage loader: A 128x32 + B 128x32 fp16 (64B rows), SW64, cp.async.
// 512 threads -> each thread one 16B chunk of A and one of B.
// ---------------------------------------------------------------------------
__device__ __forceinline__ void load_stage(
    uint32_t sbuf,
    const __half* __restrict__ aH, int lda,
    const __half* __restrict__ bH, int ldb,
    int kofs, int tid)
{
    const int row = tid >> 2, c16 = tid & 3;
    const uint32_t so = sw64((uint32_t)(row*64 + c16*16), (uint32_t)row);
    cp16(sbuf + so,           aH + (size_t)row * lda + kofs + c16*8);
    cp16(sbuf + T_BYTES + so, bH + (size_t)row * ldb + kofs + c16*8);
}

// ---------------------------------------------------------------------------
// Compute one K=32 stage. Warp tile 32x32. ALL fragments for both k16-steps
// loaded upfront (8 independent ldm4), then 16 MMAs stream stall-free.
// acc[2][4][4]  (2 m16 x 4 n8 frags) = 32 regs; frags = 32 regs.
// ---------------------------------------------------------------------------
__device__ __forceinline__ void compute_stage(uint32_t sbuf, float acc[2][4][4],
                                              int lane, int wm, int wn)
{
    const int arow0 = wm*32 + (lane & 15);
    const uint32_t aX = (uint32_t)(lane & 16);
    const int brow0 = wn*32 + (lane & 7) + ((lane & 16) >> 1);
    const uint32_t bX = (uint32_t)((lane & 8) << 1);

    uint32_t ah[2][2][4], bh[2][2][4];   // [kk][mi|g][4]
    #pragma unroll
    for (int kk = 0; kk < 2; kk++) {
        const uint32_t kb = (uint32_t)kk * 32;
        #pragma unroll
        for (int mi = 0; mi < 2; mi++) {
            const uint32_t r = (uint32_t)(arow0 + mi*16);
            ldm4(ah[kk][mi], sbuf + sw64(r*64 + kb + aX, r));
        }
        #pragma unroll
        for (int g = 0; g < 2; g++) {
            const uint32_t r = (uint32_t)(brow0 + g*16);
            ldm4(bh[kk][g], sbuf + T_BYTES + sw64(r*64 + kb + bX, r));
        }
    }
    #pragma unroll
    for (int kk = 0; kk < 2; kk++)
        #pragma unroll
        for (int mi = 0; mi < 2; mi++)
            #pragma unroll
            for (int nj = 0; nj < 4; nj++)
                mma16816(acc[mi][nj], ah[kk][mi], &bh[kk][nj>>1][(nj&1)*2]);
}

// ---------------------------------------------------------------------------
// 3-stage single-barrier pipelined mainloop (K = NC*32)
// ---------------------------------------------------------------------------
__device__ __forceinline__ void gemm_mainloop(
    const __half* __restrict__ aH, int lda,
    const __half* __restrict__ bH, int ldb,
    int NC, uint32_t sbase, float acc[2][4][4], int tid)
{
    const int lane = tid & 31, w = tid >> 5;
    const int wm = w >> 2, wn = w & 3;

    load_stage(sbase + SM_BUF, aH, lda, bH, ldb, 0, tid);
    cp_commit();
    if (NC > 1)
        load_stage(sbase + SM_BUF + STAGE_BYTES, aH, lda, bH, ldb, 32, tid);
    cp_commit();

    int s_cur = 0, s_nxt = 2 % NSTAGE;
    for (int c = 0; c < NC; c++) {
        cp_wait<1>();
        __syncthreads();
        if (c + 2 < NC)
            load_stage(sbase + SM_BUF + (uint32_t)s_nxt * STAGE_BYTES,
                       aH, lda, bH, ldb, (c+2)*32, tid);
        cp_commit();
        compute_stage(sbase + SM_BUF + (uint32_t)s_cur * STAGE_BYTES, acc, lane, wm, wn);
        s_cur = (s_cur + 1 == NSTAGE) ? 0 : s_cur + 1;
        s_nxt = (s_nxt + 1 == NSTAGE) ? 0 : s_nxt + 1;
    }
    __syncthreads();
}

// ---------------------------------------------------------------------------
extern __shared__ char dynsmem[];

// Kernel: QKV projection. grid(4 ntile, 128 mtile, 3 qkv)
__global__ __launch_bounds__(512, 1)
void proj_tc(const float* __restrict__ bq, const float* __restrict__ bk,
             const float* __restrict__ bv)
{
    const int z = blockIdx.z;
    const int m0 = blockIdx.y * 128, n0 = blockIdx.x * 128;
    const uint32_t sbase = smem_u32(dynsmem);
    const int tid = threadIdx.x;

    float acc[2][4][4];
    #pragma unroll
    for (int a = 0; a < 2; a++)
        #pragma unroll
        for (int b = 0; b < 4; b++)
            #pragma unroll
            for (int c = 0; c < 4; c++) acc[a][b][c] = 0.f;

    gemm_mainloop(g_xh + (size_t)m0 * CH, CH,
                  g_wT + (size_t)z*CH*CH + (size_t)n0 * CH, CH,
                  CH/32, sbase, acc, tid);

    const float* bias = (z == 0) ? bq : (z == 1) ? bk : bv;
    const int lane = tid & 31, w = tid >> 5;
    const int wm = w >> 2, wn = w & 3;

    #pragma unroll
    for (int mi = 0; mi < 2; mi++) {
        const int r0 = m0 + wm*32 + mi*16 + (lane >> 2);
        #pragma unroll
        for (int nj = 0; nj < 4; nj++) {
            const int n = n0 + wn*32 + nj*8 + (lane & 3)*2;
            const float b0 = bias[n], b1 = bias[n+1];
            const float v00 = acc[mi][nj][0] + b0, v01 = acc[mi][nj][1] + b1;
            const float v10 = acc[mi][nj][2] + b0, v11 = acc[mi][nj][3] + b1;
            if (z < 2) {
                __half* oH = (z == 0) ? g_qh : g_kh;
                *(__half2*)(oH + (size_t)r0*CH + n) =
                    __halves2half2(__float2half(v00), __float2half(v01));
                *(__half2*)(oH + (size_t)(r0+8)*CH + n) =
                    __halves2half2(__float2half(v10), __float2half(v11));
            } else {
                *(float2*)(g_v + (size_t)r0*CH + n)     = make_float2(v00, v01);
                *(float2*)(g_v + (size_t)(r0+8)*CH + n) = make_float2(v10, v11);
            }
        }
    }
}

// Kernel: causal scores -> exp -> E (fp16) + column partial sums.
// grid(136 tri-tiles, 8 batch), CTA tile 128x128.
__global__ __launch_bounds__(512, 1)
void scores_tc()
{
    const int b = blockIdx.y;
    int idx = blockIdx.x;
    int it = 0;
    while ((it + 1) * (it + 2) / 2 <= idx) it++;
    const int is = idx - it * (it + 1) / 2;
    const int t0 = it * 128, s0 = is * 128;

    const uint32_t sbase = smem_u32(dynsmem);
    const int tid = threadIdx.x;

    float acc[2][4][4];
    #pragma unroll
    for (int a = 0; a < 2; a++)
        #pragma unroll
        for (int c = 0; c < 4; c++)
            #pragma unroll
            for (int d = 0; d < 4; d++) acc[a][c][d] = 0.f;

    gemm_mainloop(g_qh + ((size_t)b*TT + t0)*CH, CH,
                  g_kh + ((size_t)b*TT + s0)*CH, CH,
                  CH/32, sbase, acc, tid);

    const int lane = tid & 31, w = tid >> 5;
    const int wm = w >> 2, wn = w & 3;
    float* red = (float*)dynsmem;   // [4][128]

    float psum[4][2];
    #pragma unroll
    for (int nj = 0; nj < 4; nj++) { psum[nj][0] = 0.f; psum[nj][1] = 0.f; }

    const bool diag = (it == is);
    #pragma unroll
    for (int mi = 0; mi < 2; mi++) {
        const int ta = t0 + wm*32 + mi*16 + (lane >> 2);
        const int tb = ta + 8;
        #pragma unroll
        for (int nj = 0; nj < 4; nj++) {
            const int s = s0 + wn*32 + nj*8 + (lane & 3)*2;
            float e00 = __expf(acc[mi][nj][0] * INV_SQRTK);
            float e01 = __expf(acc[mi][nj][1] * INV_SQRTK);
            float e10 = __expf(acc[mi][nj][2] * INV_SQRTK);
            float e11 = __expf(acc[mi][nj][3] * INV_SQRTK);
            if (diag) {
                if (s   > ta) e00 = 0.f;
                if (s+1 > ta) e01 = 0.f;
                if (s   > tb) e10 = 0.f;
                if (s+1 > tb) e11 = 0.f;
            }
            const size_t oa = ((size_t)b*TT + ta)*TT + s;
            const size_t ob = ((size_t)b*TT + tb)*TT + s;
            *(__half2*)(g_E + oa) = __halves2half2(__float2half(e00), __float2half(e01));
            *(__half2*)(g_E + ob) = __halves2half2(__float2half(e10), __float2half(e11));
            psum[nj][0] += e00 + e10;
            psum[nj][1] += e01 + e11;
        }
    }
    // reduce across lanes with identical (lane&3)
    #pragma unroll
    for (int ofs = 4; ofs <= 16; ofs <<= 1)
        #pragma unroll
        for (int nj = 0; nj < 4; nj++) {
            psum[nj][0] += __shfl_xor_sync(0xffffffff, psum[nj][0], ofs);
            psum[nj][1] += __shfl_xor_sync(0xffffffff, psum[nj][1], ofs);
        }
    if (lane < 4) {
        #pragma unroll
        for (int nj = 0; nj < 4; nj++) {
            const int col = wn*32 + nj*8 + lane*2;
            red[wm*128 + col]     = psum[nj][0];
            red[wm*128 + col + 1] = psum[nj][1];
        }
    }
    __syncthreads();
    if (tid < 128)
        g_part[(size_t)(b*NTILES + it)*TT + s0 + tid] =
            red[tid] + red[128 + tid] + red[256 + tid] + red[384 + tid];
}

// Kernel: reduce column partials -> reciprocal colsum
__global__ void colsum_kernel()
{
    const int i = blockIdx.x * blockDim.x + threadIdx.x;  // b*TT + s
    if (i >= BATCH*TT) return;
    const int b = i >> 11, s = i & (TT - 1);
    float sum = 0.f;
    for (int it = s >> 7; it < NTILES; it++)
        sum += g_part[(size_t)(b*NTILES + it)*TT + s];
    g_rcol[i] = 1.0f / sum;
}

// Kernel: v -> vT scaled by rcol, fp16. grid(64 s-tiles, 16 n-tiles, 8)
__global__ void convvt_kernel()
{
    __shared__ float tile[32][33];
    const int b = blockIdx.z;
    const int s0 = blockIdx.x * 32, n0 = blockIdx.y * 32;
    const int tx = threadIdx.x, ty = threadIdx.y;
    const int s = s0 + ty;
    const float scale = g_rcol[b*TT + s];
    tile[ty][tx] = g_v[((size_t)b*TT + s) * CH + n0 + tx] * scale;
    __syncthreads();
    const float v = tile[tx][ty];
    const size_t o = ((size_t)b*CH + n0 + ty) * TT + s0 + tx;
    g_vT[o] = __float2half(v);
}

// Kernel: read = E * vT'. grid(4 ntile, 16 ttile, 8 batch)
// it reversed so heavy (late-row) tiles launch first.
__global__ __launch_bounds__(512, 1)
void read_tc(float* __restrict__ out)
{
    const int b = blockIdx.z;
    const int it = NTILES - 1 - blockIdx.y;
    const int t0 = it * 128, n0 = blockIdx.x * 128;
    const uint32_t sbase = smem_u32(dynsmem);
    const int tid = threadIdx.x;

    float acc[2][4][4];
    #pragma unroll
    for (int a = 0; a < 2; a++)
        #pragma unroll
        for (int c = 0; c < 4; c++)
            #pragma unroll
            for (int d = 0; d < 4; d++) acc[a][c][d] = 0.f;

    gemm_mainloop(g_E + ((size_t)b*TT + t0)*TT, TT,
                  g_vT + ((size_t)b*CH + n0)*TT, TT,
                  (it + 1) * 4, sbase, acc, tid);

    const int lane = tid & 31, w = tid >> 5;
    const int wm = w >> 2, wn = w & 3;

    #pragma unroll
    for (int mi = 0; mi < 2; mi++) {
        const int t = t0 + wm*32 + mi*16 + (lane >> 2);
        #pragma unroll
        for (int nj = 0; nj < 4; nj++) {
            const int n = n0 + wn*32 + nj*8 + (lane & 3)*2;
            float* oa = out + ((size_t)(b*TT + t)) * 1024 + 512 + n;
            float* ob = out + ((size_t)(b*TT + t + 8)) * 1024 + 512 + n;
            *(float2*)oa = make_float2(acc[mi][nj][0], acc[mi][nj][1]);
            *(float2*)ob = make_float2(acc[mi][nj][2], acc[mi][nj][3]);
        }
    }
}

// ---------------------------------------------------------------------------
// x prep: copy x into out[:, 0:512] AND convert to fp16 in one pass
// ---------------------------------------------------------------------------
__global__ void xprep_kernel(const float* __restrict__ x, float* __restrict__ out)
{
    const size_t i = (size_t)blockIdx.x * blockDim.x + threadIdx.x;  // float4 idx
    const int row = (int)(i >> 7), c4 = (int)(i & 127);
    const float4 v = ((const float4*)x)[i];
    ((float4*)out)[(size_t)row * 256 + c4] = v;
    __align__(8) __half h[4];
    h[0] = __float2half(v.x); h[1] = __float2half(v.y);
    h[2] = __float2half(v.z); h[3] = __float2half(v.w);
    ((uint2*)g_xh)[i] = *(const uint2*)h;
}

__global__ void convw_kernel(const float* __restrict__ Wq,
                             const float* __restrict__ Wk,
                             const float* __restrict__ Wv)
{
    __shared__ float tile[32][33];
    const float* W = (blockIdx.z == 0) ? Wq : (blockIdx.z == 1) ? Wk : Wv;
    const int k0 = blockIdx.x * 32, n0 = blockIdx.y * 32;
    const int tx = threadIdx.x, ty = threadIdx.y;
    tile[ty][tx] = W[(size_t)(k0 + ty) * CH + n0 + tx];
    __syncthreads();
    const float v = tile[tx][ty];   // = W[k0+tx][n0+ty]
    const size_t o = (size_t)blockIdx.z*CH*CH + (size_t)(n0 + ty) * CH + k0 + tx;
    g_wT[o] = __float2half(v);
}

// ---------------------------------------------------------------------------
extern "C" void kernel_launch(void* const* d_in, const int* in_sizes, int n_in,
                              void* d_out, int out_size)
{
    const float* x  = (const float*)d_in[0];
    const float* Wq = (const float*)d_in[1];
    const float* bq = (const float*)d_in[2];
    const float* Wk = (const float*)d_in[3];
    const float* bk = (const float*)d_in[4];
    const float* Wv = (const float*)d_in[5];
    const float* bv = (const float*)d_in[6];
    float* out = (float*)d_out;

    cudaFuncSetAttribute(proj_tc,   cudaFuncAttributeMaxDynamicSharedMemorySize, SMEM_TOTAL);
    cudaFuncSetAttribute(scores_tc, cudaFuncAttributeMaxDynamicSharedMemorySize, SMEM_TOTAL);
    cudaFuncSetAttribute(read_tc,   cudaFuncAttributeMaxDynamicSharedMemorySize, SMEM_TOTAL);

    xprep_kernel<<<8192, 256>>>(x, out);
    convw_kernel<<<dim3(16, 16, 3), dim3(32, 32)>>>(Wq, Wk, Wv);
    proj_tc<<<dim3(4, 128, 3), 512, SMEM_TOTAL>>>(bq, bk, bv);
    scores_tc<<<dim3(136, BATCH), 512, SMEM_TOTAL>>>();
    colsum_kernel<<<64, 256>>>();
    convvt_kernel<<<dim3(64, 16, 8), dim3(32, 32)>>>();
    read_tc<<<dim3(4, NTILES, BATCH), 512, SMEM_TOTAL>>>(out);
}

// round 14
// speedup vs baseline: 1.2602x; 1.1851x over previous
#include <cuda_runtime.h>
#include <cuda_fp16.h>
#include <cstdint>

// ---------------------------------------------------------------------------
// Problem constants
// ---------------------------------------------------------------------------
#define BATCH 8
#define TT 2048
#define CH 512
#define MTOT (BATCH*TT)          // 16384
#define NTILES (TT/128)          // 16 row tiles
#define INV_SQRTK 0.04419417382415922f

// ---------------------------------------------------------------------------
// CTA: 256 threads, 8 warps in 2(M)x4(N), warp tile 64x32 -> CTA tile 128x128.
// K-chunk 64 (128-byte rows, SW128 swizzle).
// Shared memory (dynamic):
//   [0:1024)          reduction scratch (scores)
//   [1024: +3*32KB)   three stages x {A: 128x64 (16KB), B: 128x64 (16KB)}
// 97KB/CTA -> 2 CTAs per SM (194KB of 228KB). 128 regs/thread.
// ---------------------------------------------------------------------------
#define SM_RED 0
#define SM_BUF 1024
#define T_BYTES 16384
#define STAGE_BYTES (2*T_BYTES)
#define NSTAGE 3
#define SMEM_TOTAL (1024 + NSTAGE*STAGE_BYTES)   // 99328

// ---------------------------------------------------------------------------
// Device scratch (no allocation allowed). Pure fp16 operands.
// ---------------------------------------------------------------------------
__device__ __align__(16) __half g_xh[(size_t)MTOT*CH];
__device__ __align__(16) __half g_wT[(size_t)3*CH*CH];
__device__ __align__(16) __half g_qh[(size_t)MTOT*CH];
__device__ __align__(16) __half g_kh[(size_t)MTOT*CH];
__device__ __align__(16) float  g_v[(size_t)MTOT*CH];
__device__ __align__(16) __half g_E[(size_t)BATCH*TT*TT];
__device__ __align__(16) __half g_vT[(size_t)BATCH*CH*TT];
__device__ float g_part[BATCH*NTILES*TT];
__device__ float g_rcol[BATCH*TT];

// ---------------------------------------------------------------------------
// PTX helpers — portable (sm_80-level) PTX, legal at compute_103
// ---------------------------------------------------------------------------
__device__ __forceinline__ uint32_t smem_u32(const void* p) {
    uint32_t a;
    asm("{ .reg .u64 t; cvta.to.shared.u64 t, %1; cvt.u32.u64 %0, t; }"
        : "=r"(a) : "l"(p));
    return a;
}

__device__ __forceinline__ void cp16(uint32_t s, const void* g) {
    asm volatile("cp.async.cg.shared.global [%0], [%1], 16;" :: "r"(s), "l"(g));
}
__device__ __forceinline__ void cp_commit() {
    asm volatile("cp.async.commit_group;" ::: "memory");
}
template<int N> __device__ __forceinline__ void cp_wait() {
    asm volatile("cp.async.wait_group %0;" :: "n"(N) : "memory");
}

__device__ __forceinline__ void ldm4(uint32_t* r, uint32_t a) {
    asm volatile("ldmatrix.sync.aligned.m8n8.x4.shared.b16 {%0,%1,%2,%3}, [%4];"
        : "=r"(r[0]), "=r"(r[1]), "=r"(r[2]), "=r"(r[3]) : "r"(a));
}

__device__ __forceinline__ void mma16816(float* c, const uint32_t* a, const uint32_t* b) {
    asm volatile(
        "mma.sync.aligned.m16n8k16.row.col.f32.f16.f16.f32 "
        "{%0,%1,%2,%3}, {%4,%5,%6,%7}, {%8,%9}, {%0,%1,%2,%3};"
        : "+f"(c[0]), "+f"(c[1]), "+f"(c[2]), "+f"(c[3])
        : "r"(a[0]), "r"(a[1]), "r"(a[2]), "r"(a[3]), "r"(b[0]), "r"(b[1]));
}

// ---------------------------------------------------------------------------
// Stage loader: A 128x64 + B 128x64 fp16 (128B rows), SW128 swizzle, cp.async.
// 256 threads: each loads 4 chunks of A and 4 of B (16B each).
// ---------------------------------------------------------------------------
__device__ __forceinline__ void load_stage(
    uint32_t sbuf,
    const __half* __restrict__ aH, int lda,
    const __half* __restrict__ bH, int ldb,
    int kofs, int tid)
{
    #pragma unroll
    for (int i = 0; i < 4; i++) {
        const int u = tid + i*256;
        const int row = u >> 3, cg = u & 7;
        const uint32_t so = (uint32_t)(row*128) + (uint32_t)((cg*16) ^ ((row & 7) << 4));
        cp16(sbuf + so,           aH + (size_t)row * lda + kofs + cg*8);
        cp16(sbuf + T_BYTES + so, bH + (size_t)row * ldb + kofs + cg*8);
    }
}

// ---------------------------------------------------------------------------
// Compute one K=64 stage: 4 k16-steps; per step 6 ldm4 feed 16 MMAs.
// Warp grid 2(M)x4(N); warp tile 64x32; acc[4][4][4] (identical to R10 inner)
// ---------------------------------------------------------------------------
__device__ __forceinline__ void compute_stage(uint32_t sbuf, float acc[4][4][4],
                                              int lane, int wm, int wn)
{
    const int arow = wm*64 + (lane & 15);
    const uint32_t aX = (uint32_t)(lane & 16);
    const int brow = wn*32 + (lane & 7) + ((lane & 16) >> 1);
    const uint32_t bX = (uint32_t)((lane & 8) << 1);
    const uint32_t axor = (uint32_t)((arow & 7) << 4);
    const uint32_t bxor = (uint32_t)((lane & 7) << 4);

    #pragma unroll
    for (int kk = 0; kk < 4; kk++) {
        const uint32_t kb = (uint32_t)kk * 32;
        const uint32_t acol = (kb + aX) ^ axor;
        const uint32_t bcol = (kb + bX) ^ bxor;
        uint32_t ah[4][4], bh[2][4];
        #pragma unroll
        for (int g = 0; g < 2; g++)
            ldm4(bh[g], sbuf + T_BYTES + (uint32_t)((brow + g*16)*128) + bcol);
        #pragma unroll
        for (int mi = 0; mi < 4; mi++)
            ldm4(ah[mi], sbuf + (uint32_t)((arow + mi*16)*128) + acol);
        #pragma unroll
        for (int mi = 0; mi < 4; mi++)
            #pragma unroll
            for (int nj = 0; nj < 4; nj++)
                mma16816(acc[mi][nj], ah[mi], &bh[nj>>1][(nj&1)*2]);
    }
}

// ---------------------------------------------------------------------------
// 3-stage single-barrier pipelined mainloop (K = NC*64)
// ---------------------------------------------------------------------------
__device__ __forceinline__ void gemm_mainloop(
    const __half* __restrict__ aH, int lda,
    const __half* __restrict__ bH, int ldb,
    int NC, uint32_t sbase, float acc[4][4][4], int tid)
{
    const int lane = tid & 31, w = tid >> 5;
    const int wm = w >> 2, wn = w & 3;

    load_stage(sbase + SM_BUF, aH, lda, bH, ldb, 0, tid);
    cp_commit();
    if (NC > 1)
        load_stage(sbase + SM_BUF + STAGE_BYTES, aH, lda, bH, ldb, 64, tid);
    cp_commit();

    int s_cur = 0, s_nxt = 2 % NSTAGE;
    for (int c = 0; c < NC; c++) {
        cp_wait<1>();
        __syncthreads();
        if (c + 2 < NC)
            load_stage(sbase + SM_BUF + (uint32_t)s_nxt * STAGE_BYTES,
                       aH, lda, bH, ldb, (c+2)*64, tid);
        cp_commit();
        compute_stage(sbase + SM_BUF + (uint32_t)s_cur * STAGE_BYTES, acc, lane, wm, wn);
        s_cur = (s_cur + 1 == NSTAGE) ? 0 : s_cur + 1;
        s_nxt = (s_nxt + 1 == NSTAGE) ? 0 : s_nxt + 1;
    }
    __syncthreads();
}

// ---------------------------------------------------------------------------
extern __shared__ char dynsmem[];

// Kernel: QKV projection. grid(4 ntile, 128 mtile, 3 qkv)
__global__ __launch_bounds__(256, 2)
void proj_tc(const float* __restrict__ bq, const float* __restrict__ bk,
             const float* __restrict__ bv)
{
    const int z = blockIdx.z;
    const int m0 = blockIdx.y * 128, n0 = blockIdx.x * 128;
    const uint32_t sbase = smem_u32(dynsmem);
    const int tid = threadIdx.x;

    float acc[4][4][4];
    #pragma unroll
    for (int a = 0; a < 4; a++)
        #pragma unroll
        for (int b = 0; b < 4; b++)
            #pragma unroll
            for (int c = 0; c < 4; c++) acc[a][b][c] = 0.f;

    gemm_mainloop(g_xh + (size_t)m0 * CH, CH,
                  g_wT + (size_t)z*CH*CH + (size_t)n0 * CH, CH,
                  CH/64, sbase, acc, tid);

    const float* bias = (z == 0) ? bq : (z == 1) ? bk : bv;
    const int lane = tid & 31, w = tid >> 5;
    const int wm = w >> 2, wn = w & 3;

    #pragma unroll
    for (int mi = 0; mi < 4; mi++) {
        const int r0 = m0 + wm*64 + mi*16 + (lane >> 2);
        #pragma unroll
        for (int nj = 0; nj < 4; nj++) {
            const int n = n0 + wn*32 + nj*8 + (lane & 3)*2;
            const float b0 = bias[n], b1 = bias[n+1];
            const float v00 = acc[mi][nj][0] + b0, v01 = acc[mi][nj][1] + b1;
            const float v10 = acc[mi][nj][2] + b0, v11 = acc[mi][nj][3] + b1;
            if (z < 2) {
                __half* oH = (z == 0) ? g_qh : g_kh;
                *(__half2*)(oH + (size_t)r0*CH + n) =
                    __halves2half2(__float2half(v00), __float2half(v01));
                *(__half2*)(oH + (size_t)(r0+8)*CH + n) =
                    __halves2half2(__float2half(v10), __float2half(v11));
            } else {
                *(float2*)(g_v + (size_t)r0*CH + n)     = make_float2(v00, v01);
                *(float2*)(g_v + (size_t)(r0+8)*CH + n) = make_float2(v10, v11);
            }
        }
    }
}

// Kernel: causal scores -> exp -> E (fp16) + column partial sums.
// grid(136 tri-tiles, 8 batch), CTA tile 128x128.
__global__ __launch_bounds__(256, 2)
void scores_tc()
{
    const int b = blockIdx.y;
    int idx = blockIdx.x;
    int it = 0;
    while ((it + 1) * (it + 2) / 2 <= idx) it++;
    const int is = idx - it * (it + 1) / 2;
    const int t0 = it * 128, s0 = is * 128;

    const uint32_t sbase = smem_u32(dynsmem);
    const int tid = threadIdx.x;

    float acc[4][4][4];
    #pragma unroll
    for (int a = 0; a < 4; a++)
        #pragma unroll
        for (int c = 0; c < 4; c++)
            #pragma unroll
            for (int d = 0; d < 4; d++) acc[a][c][d] = 0.f;

    gemm_mainloop(g_qh + ((size_t)b*TT + t0)*CH, CH,
                  g_kh + ((size_t)b*TT + s0)*CH, CH,
                  CH/64, sbase, acc, tid);

    const int lane = tid & 31, w = tid >> 5;
    const int wm = w >> 2, wn = w & 3;
    float* red = (float*)dynsmem;   // [2][128]

    float psum[4][2];
    #pragma unroll
    for (int nj = 0; nj < 4; nj++) { psum[nj][0] = 0.f; psum[nj][1] = 0.f; }

    const bool diag = (it == is);
    #pragma unroll
    for (int mi = 0; mi < 4; mi++) {
        const int ta = t0 + wm*64 + mi*16 + (lane >> 2);
        const int tb = ta + 8;
        #pragma unroll
        for (int nj = 0; nj < 4; nj++) {
            const int s = s0 + wn*32 + nj*8 + (lane & 3)*2;
            float e00 = __expf(acc[mi][nj][0] * INV_SQRTK);
            float e01 = __expf(acc[mi][nj][1] * INV_SQRTK);
            float e10 = __expf(acc[mi][nj][2] * INV_SQRTK);
            float e11 = __expf(acc[mi][nj][3] * INV_SQRTK);
            if (diag) {
                if (s   > ta) e00 = 0.f;
                if (s+1 > ta) e01 = 0.f;
                if (s   > tb) e10 = 0.f;
                if (s+1 > tb) e11 = 0.f;
            }
            const size_t oa = ((size_t)b*TT + ta)*TT + s;
            const size_t ob = ((size_t)b*TT + tb)*TT + s;
            *(__half2*)(g_E + oa) = __halves2half2(__float2half(e00), __float2half(e01));
            *(__half2*)(g_E + ob) = __halves2half2(__float2half(e10), __float2half(e11));
            psum[nj][0] += e00 + e10;
            psum[nj][1] += e01 + e11;
        }
    }
    #pragma unroll
    for (int ofs = 4; ofs <= 16; ofs <<= 1)
        #pragma unroll
        for (int nj = 0; nj < 4; nj++) {
            psum[nj][0] += __shfl_xor_sync(0xffffffff, psum[nj][0], ofs);
            psum[nj][1] += __shfl_xor_sync(0xffffffff, psum[nj][1], ofs);
        }
    if (lane < 4) {
        #pragma unroll
        for (int nj = 0; nj < 4; nj++) {
            const int col = wn*32 + nj*8 + lane*2;
            red[wm*128 + col]     = psum[nj][0];
            red[wm*128 + col + 1] = psum[nj][1];
        }
    }
    __syncthreads();
    if (tid < 128)
        g_part[(size_t)(b*NTILES + it)*TT + s0 + tid] = red[tid] + red[128 + tid];
}

// Kernel: reduce column partials -> reciprocal colsum
__global__ void colsum_kernel()
{
    const int i = blockIdx.x * blockDim.x + threadIdx.x;  // b*TT + s
    if (i >= BATCH*TT) return;
    const int b = i >> 11, s = i & (TT - 1);
    float sum = 0.f;
    for (int it = s >> 7; it < NTILES; it++)
        sum += g_part[(size_t)(b*NTILES + it)*TT + s];
    g_rcol[i] = 1.0f / sum;
}

// Kernel: v -> vT scaled by rcol, fp16. grid(64 s-tiles, 16 n-tiles, 8)
__global__ void convvt_kernel()
{
    __shared__ float tile[32][33];
    const int b = blockIdx.z;
    const int s0 = blockIdx.x * 32, n0 = blockIdx.y * 32;
    const int tx = threadIdx.x, ty = threadIdx.y;
    const int s = s0 + ty;
    const float scale = g_rcol[b*TT + s];
    tile[ty][tx] = g_v[((size_t)b*TT + s) * CH + n0 + tx] * scale;
    __syncthreads();
    const float v = tile[tx][ty];
    const size_t o = ((size_t)b*CH + n0 + ty) * TT + s0 + tx;
    g_vT[o] = __float2half(v);
}

// Kernel: read = E * vT'. grid(4 ntile, 16 ttile, 8 batch)
// it reversed so heavy (late-row) tiles launch first.
__global__ __launch_bounds__(256, 2)
void read_tc(float* __restrict__ out)
{
    const int b = blockIdx.z;
    const int it = NTILES - 1 - blockIdx.y;
    const int t0 = it * 128, n0 = blockIdx.x * 128;
    const uint32_t sbase = smem_u32(dynsmem);
    const int tid = threadIdx.x;

    float acc[4][4][4];
    #pragma unroll
    for (int a = 0; a < 4; a++)
        #pragma unroll
        for (int c = 0; c < 4; c++)
            #pragma unroll
            for (int d = 0; d < 4; d++) acc[a][c][d] = 0.f;

    gemm_mainloop(g_E + ((size_t)b*TT + t0)*TT, TT,
                  g_vT + ((size_t)b*CH + n0)*TT, TT,
                  (it + 1) * 2, sbase, acc, tid);

    const int lane = tid & 31, w = tid >> 5;
    const int wm = w >> 2, wn = w & 3;

    #pragma unroll
    for (int mi = 0; mi < 4; mi++) {
        const int t = t0 + wm*64 + mi*16 + (lane >> 2);
        #pragma unroll
        for (int nj = 0; nj < 4; nj++) {
            const int n = n0 + wn*32 + nj*8 + (lane & 3)*2;
            float* oa = out + ((size_t)(b*TT + t)) * 1024 + 512 + n;
            float* ob = out + ((size_t)(b*TT + t + 8)) * 1024 + 512 + n;
            *(float2*)oa = make_float2(acc[mi][nj][0], acc[mi][nj][1]);
            *(float2*)ob = make_float2(acc[mi][nj][2], acc[mi][nj][3]);
        }
    }
}

// ---------------------------------------------------------------------------
// x prep: copy x into out[:, 0:512] AND convert to fp16 in one pass
// ---------------------------------------------------------------------------
__global__ void xprep_kernel(const float* __restrict__ x, float* __restrict__ out)
{
    const size_t i = (size_t)blockIdx.x * blockDim.x + threadIdx.x;  // float4 idx
    const int row = (int)(i >> 7), c4 = (int)(i & 127);
    const float4 v = ((const float4*)x)[i];
    ((float4*)out)[(size_t)row * 256 + c4] = v;
    __align__(8) __half h[4];
    h[0] = __float2half(v.x); h[1] = __float2half(v.y);
    h[2] = __float2half(v.z); h[3] = __float2half(v.w);
    ((uint2*)g_xh)[i] = *(const uint2*)h;
}

__global__ void convw_kernel(const float* __restrict__ Wq,
                             const float* __restrict__ Wk,
                             const float* __restrict__ Wv)
{
    __shared__ float tile[32][33];
    const float* W = (blockIdx.z == 0) ? Wq : (blockIdx.z == 1) ? Wk : Wv;
    const int k0 = blockIdx.x * 32, n0 = blockIdx.y * 32;
    const int tx = threadIdx.x, ty = threadIdx.y;
    tile[ty][tx] = W[(size_t)(k0 + ty) * CH + n0 + tx];
    __syncthreads();
    const float v = tile[tx][ty];   // = W[k0+tx][n0+ty]
    const size_t o = (size_t)blockIdx.z*CH*CH + (size_t)(n0 + ty) * CH + k0 + tx;
    g_wT[o] = __float2half(v);
}

// ---------------------------------------------------------------------------
extern "C" void kernel_launch(void* const* d_in, const int* in_sizes, int n_in,
                              void* d_out, int out_size)
{
    const float* x  = (const float*)d_in[0];
    const float* Wq = (const float*)d_in[1];
    const float* bq = (const float*)d_in[2];
    const float* Wk = (const float*)d_in[3];
    const float* bk = (const float*)d_in[4];
    const float* Wv = (const float*)d_in[5];
    const float* bv = (const float*)d_in[6];
    float* out = (float*)d_out;

    cudaFuncSetAttribute(proj_tc,   cudaFuncAttributeMaxDynamicSharedMemorySize, SMEM_TOTAL);
    cudaFuncSetAttribute(scores_tc, cudaFuncAttributeMaxDynamicSharedMemorySize, SMEM_TOTAL);
    cudaFuncSetAttribute(read_tc,   cudaFuncAttributeMaxDynamicSharedMemorySize, SMEM_TOTAL);

    xprep_kernel<<<8192, 256>>>(x, out);
    convw_kernel<<<dim3(16, 16, 3), dim3(32, 32)>>>(Wq, Wk, Wv);
    proj_tc<<<dim3(4, 128, 3), 256, SMEM_TOTAL>>>(bq, bk, bv);
    scores_tc<<<dim3(136, BATCH), 256, SMEM_TOTAL>>>();
    colsum_kernel<<<64, 256>>>();
    convvt_kernel<<<dim3(64, 16, 8), dim3(32, 32)>>>();
    read_tc<<<dim3(4, NTILES, BATCH), 256, SMEM_TOTAL>>>(out);
}